// round 5
// baseline (speedup 1.0000x reference)
#include <cuda_runtime.h>

// Problem: x [B=8, C=64, H=64, W=64], N = H*W = 4096
// out = [ y (B*C*N fp32) | attn (B*N*N fp32) ]
#define BATCH 8
#define CDIM  64
#define NDIM  4096
#define NN    (NDIM * NDIM)
#define Y_ELEMS (BATCH * CDIM * NDIM)

typedef unsigned long long ull;

// Scratch (device globals: allocation-free scratch per harness rules)
__device__ float g_diag[BATCH * NDIM];  // ||x_n||^2  (softmax shift)
__device__ float g_sums[BATCH * NDIM];  // sum_m exp(s - d_n)

// ---------------------------------------------------------------------------
// Packed f32x2 (sm_103a FFMA2 — 2x fp32 FMA throughput, PTX-only)
// ---------------------------------------------------------------------------
__device__ __forceinline__ ull pack2(float lo, float hi) {
    ull r; asm("mov.b64 %0, {%1, %2};" : "=l"(r) : "f"(lo), "f"(hi)); return r;
}
__device__ __forceinline__ void unpack2(float& lo, float& hi, ull v) {
    asm("mov.b64 {%0, %1}, %2;" : "=f"(lo), "=f"(hi) : "l"(v));
}
__device__ __forceinline__ void ffma2(ull& d, ull a, ull b) {
    asm("fma.rn.f32x2 %0, %1, %2, %0;" : "+l"(d) : "l"(a), "l"(b));
}

// ---------------------------------------------------------------------------
// A: diag norms + zero the row-sum accumulator.
// ---------------------------------------------------------------------------
__global__ void prep_kernel(const float* __restrict__ x) {
    int idx = blockIdx.x * 256 + threadIdx.x;       // [0, BATCH*NDIM)
    int b = idx >> 12;
    int n = idx & (NDIM - 1);
    const float* xb = x + (size_t)b * (CDIM * NDIM);
    float s = 0.0f;
#pragma unroll
    for (int c = 0; c < CDIM; c++) {
        float v = xb[c * NDIM + n];
        s = fmaf(v, v, s);
    }
    g_diag[idx] = s;
    g_sums[idx] = 0.0f;
}

// ---------------------------------------------------------------------------
// B: upper-triangle Gram tiles. For tile block (bi <= bj):
//    compute s = <x_n, x_m> (128x128), write exp(s - d_n) at [n][m],
//    and (if bi != bj) exp(s - d_m) at [m][n] via smem transpose staging.
//    Accumulate per-row sums of exp into g_sums (shuffle + atomicAdd).
// 256 threads (16x16); thread owns 8 rows (ty+16i) x 4 col-pairs (2tx+32u).
// ---------------------------------------------------------------------------
__global__ __launch_bounds__(256, 2)
void scores_exp_kernel(const float* __restrict__ x, float* __restrict__ attn) {
    __shared__ float S[2][32][128];   // S[0]=Q chunk (n-block), S[1]=K chunk (m-block)

    const int t  = threadIdx.x;
    const int tx = t & 15;
    const int ty = t >> 4;
    const int b  = blockIdx.y;

    // Triangle decode: k -> (bi, bj), bi <= bj, k = bj*(bj+1)/2 + bi
    int k = blockIdx.x;
    int bj = (int)((sqrtf(8.0f * (float)k + 1.0f) - 1.0f) * 0.5f);
    while ((bj + 1) * (bj + 2) / 2 <= k) bj++;
    while (bj * (bj + 1) / 2 > k) bj--;
    int bi = k - bj * (bj + 1) / 2;

    const int n0 = bi * 128;
    const int m0 = bj * 128;
    const float* xb = x + (size_t)b * (CDIM * NDIM);

    ull acc[8][4];
#pragma unroll
    for (int i = 0; i < 8; i++)
#pragma unroll
        for (int u = 0; u < 4; u++) acc[i][u] = 0ULL;

    for (int cc = 0; cc < CDIM; cc += 32) {
#pragma unroll
        for (int kk = 0; kk < 16; kk++) {
            int idx = t + kk * 256;
            int cl  = idx >> 7;
            int j   = idx & 127;
            S[0][cl][j] = xb[(cc + cl) * NDIM + n0 + j];
            S[1][cl][j] = xb[(cc + cl) * NDIM + m0 + j];
        }
        __syncthreads();

#pragma unroll
        for (int cl = 0; cl < 32; cl++) {
            ull b2[4];
#pragma unroll
            for (int u = 0; u < 4; u++)   // 8B-strided lanes: conflict-free LDS.64
                b2[u] = *(const ull*)&S[1][cl][2 * tx + 32 * u];
#pragma unroll
            for (int i = 0; i < 8; i++) {
                float a = S[0][cl][ty + 16 * i];
                ull a2 = pack2(a, a);
#pragma unroll
                for (int u = 0; u < 4; u++) ffma2(acc[i][u], a2, b2[u]);
            }
        }
        __syncthreads();
    }

    const float* diag = g_diag + b * NDIM;
    float* sums = g_sums + b * NDIM;
    float* ab = attn + (size_t)b * NN;

    // --- Phase 1: original orientation [n][m], shift d_n ---
#pragma unroll
    for (int i = 0; i < 8; i++) {
        int r = ty + 16 * i;
        float dn = diag[n0 + r];
        float rs = 0.0f;
        size_t base = (size_t)(n0 + r) * NDIM + m0;
#pragma unroll
        for (int u = 0; u < 4; u++) {
            float lo, hi;
            unpack2(lo, hi, acc[i][u]);
            float el = __expf(lo - dn);
            float eh = __expf(hi - dn);
            *(float2*)&ab[base + 2 * tx + 32 * u] = make_float2(el, eh);
            rs += el + eh;
        }
        // reduce across the 16 tx lanes of each half-warp (same row set)
        rs += __shfl_xor_sync(0xffffffffu, rs, 1);
        rs += __shfl_xor_sync(0xffffffffu, rs, 2);
        rs += __shfl_xor_sync(0xffffffffu, rs, 4);
        rs += __shfl_xor_sync(0xffffffffu, rs, 8);
        if ((t & 15) == 0) atomicAdd(&sums[n0 + r], rs);
    }

    // --- Phase 2: transposed orientation [m][n], shift d_m (off-diag only) ---
    if (bi != bj) {
        // Reuse the (now dead) smem: 32x129 staging tile. Pitch 129 makes the
        // scatter stores Ts[2tx+p][ty+16i] hit 32 distinct banks per warp.
        float (*Ts)[129] = (float (*)[129]) & S[0][0][0];
#pragma unroll
        for (int u = 0; u < 4; u++) {
            int cb = m0 + 2 * tx + 32 * u;
            float dml = diag[cb];
            float dmh = diag[cb + 1];
            float csl = 0.0f, csh = 0.0f;
#pragma unroll
            for (int i = 0; i < 8; i++) {
                float lo, hi;
                unpack2(lo, hi, acc[i][u]);
                float el = __expf(lo - dml);
                float eh = __expf(hi - dmh);
                int r = ty + 16 * i;
                Ts[2 * tx][r]     = el;
                Ts[2 * tx + 1][r] = eh;
                csl += el;
                csh += eh;
            }
            __syncthreads();
            // coalesced write of 32 m-rows x 128 n-cols
#pragma unroll
            for (int kk = 0; kk < 16; kk++) {
                int idx = t + kk * 256;
                int c  = idx >> 7;
                int r2 = idx & 127;
                ab[(size_t)(m0 + 32 * u + c) * NDIM + n0 + r2] = Ts[c][r2];
            }
            __syncthreads();
            // column sums: xor-16 combines the two ty values in this warp
            csl += __shfl_xor_sync(0xffffffffu, csl, 16);
            csh += __shfl_xor_sync(0xffffffffu, csh, 16);
            if ((t & 31) < 16) {
                atomicAdd(&sums[cb], csl);
                atomicAdd(&sums[cb + 1], csh);
            }
        }
    }
}

// ---------------------------------------------------------------------------
// C: fused normalize + y = attn @ X^T.
// Loads unnormalized exp tile, scales by 1/rowsum, writes the normalized
// value back (in-place, coalesced) AND uses it for the FFMA2 GEMM.
// ---------------------------------------------------------------------------
__global__ __launch_bounds__(256, 2)
void av_norm_kernel(const float* __restrict__ x, float* __restrict__ attn,
                    float* __restrict__ y) {
    __shared__ float As[32][130];
    __shared__ float Xs[32][65];
    __shared__ float invS[128];

    const int t  = threadIdx.x;
    const int tx = t & 15;
    const int ty = t >> 4;
    const int n0 = blockIdx.x * 128;
    const int b  = blockIdx.y;
    const float* xb = x + (size_t)b * (CDIM * NDIM);
    float* ab = attn + (size_t)b * NN;

    if (t < 128) invS[t] = 1.0f / g_sums[b * NDIM + n0 + t];
    __syncthreads();

    ull acc[4][4];
#pragma unroll
    for (int i = 0; i < 4; i++)
#pragma unroll
        for (int u = 0; u < 4; u++) acc[i][u] = 0ULL;

    for (int m0 = 0; m0 < NDIM; m0 += 32) {
        // load + normalize + writeback + transpose-stage
#pragma unroll
        for (int kk = 0; kk < 16; kk++) {
            int idx = t + kk * 256;
            int r = idx >> 5;
            int j = idx & 31;
            size_t off = (size_t)(n0 + r) * NDIM + m0 + j;
            float p = ab[off] * invS[r];
            ab[off] = p;          // final normalized attn (coalesced, in-place)
            As[j][r] = p;
        }
#pragma unroll
        for (int kk = 0; kk < 8; kk++) {
            int idx = t + kk * 256;
            int c = idx >> 5;
            int j = idx & 31;
            Xs[j][c] = xb[c * NDIM + m0 + j];
        }
        __syncthreads();

#pragma unroll
        for (int mm = 0; mm < 32; mm++) {
            ull a2[4];
#pragma unroll
            for (int i = 0; i < 4; i++)   // 8B-aligned row pairs (130*4 % 8 == 0)
                a2[i] = *(const ull*)&As[mm][2 * ty + 32 * i];
#pragma unroll
            for (int u = 0; u < 4; u++) {
                float bv = Xs[mm][tx + 16 * u];
                ull b2 = pack2(bv, bv);
#pragma unroll
                for (int i = 0; i < 4; i++) ffma2(acc[i][u], a2[i], b2);
            }
        }
        __syncthreads();
    }

#pragma unroll
    for (int u = 0; u < 4; u++) {
        int c = tx + 16 * u;
#pragma unroll
        for (int i = 0; i < 4; i++) {
            float lo, hi;
            unpack2(lo, hi, acc[i][u]);
            int n = n0 + 2 * ty + 32 * i;
            *(float2*)&y[(size_t)b * (CDIM * NDIM) + (size_t)c * NDIM + n] =
                make_float2(lo, hi);
        }
    }
}

// ---------------------------------------------------------------------------
// Launch. d_in[0] = x. d_out = [ y | attn ]. Graph-capturable, alloc-free.
// ---------------------------------------------------------------------------
extern "C" void kernel_launch(void* const* d_in, const int* in_sizes, int n_in,
                              void* d_out, int out_size) {
    (void)in_sizes; (void)n_in; (void)out_size;
    const float* x = (const float*)d_in[0];
    float* out  = (float*)d_out;
    float* y    = out;
    float* attn = out + Y_ELEMS;

    prep_kernel<<<(BATCH * NDIM) / 256, 256>>>(x);

    dim3 gB(528, BATCH);                 // 32*33/2 triangle tiles per batch
    scores_exp_kernel<<<gB, 256>>>(x, attn);

    dim3 gC(NDIM / 128, BATCH);          // (32, 8): one full wave @ occ 2
    av_norm_kernel<<<gC, 256>>>(x, attn, y);
}

// round 6
// speedup vs baseline: 1.2457x; 1.2457x over previous
#include <cuda_runtime.h>

// Problem: x [B=8, C=64, H=64, W=64], N = H*W = 4096
// out = [ y (B*C*N fp32) | attn (B*N*N fp32) ]
#define BATCH 8
#define CDIM  64
#define NDIM  4096
#define NN    (NDIM * NDIM)
#define Y_ELEMS (BATCH * CDIM * NDIM)

typedef unsigned long long ull;

// ---------------------------------------------------------------------------
// Packed f32x2 (sm_103a FFMA2 — 2x fp32 FMA throughput, PTX-only)
// ---------------------------------------------------------------------------
__device__ __forceinline__ void unpack2(float& lo, float& hi, ull v) {
    asm("mov.b64 {%0, %1}, %2;" : "=f"(lo), "=f"(hi) : "l"(v));
}
__device__ __forceinline__ void ffma2(ull& d, ull a, ull b) {
    asm("fma.rn.f32x2 %0, %1, %2, %0;" : "+l"(d) : "l"(a), "l"(b));
}

// ---------------------------------------------------------------------------
// K1: raw scores S[b][n][m] = sum_c x[b][c][n] * x[b][c][m]
// 128x128 tile per CTA, 512 threads (16x32), per-thread 4 rows x 4 col-pairs.
// Q stored DUPLICATED in smem so the dup'd FFMA2 operand is one broadcast
// LDS.64 (no packs). Inner loop: 4+4 LDS.64 + 16 FFMA2 = 24 instr, 67% fma.
// occ 2 => 32 warps/SM = 8/SMSP (vs 4 before) for latency hiding.
// ---------------------------------------------------------------------------
__global__ __launch_bounds__(512, 2)
void scores_kernel(const float* __restrict__ x, float* __restrict__ attn) {
    __shared__ float Qd[32][256];   // Q chunk, each value duplicated: (q,q)
    __shared__ float Ks[32][128];   // K chunk

    const int t  = threadIdx.x;
    const int tx = t & 15;          // col group: cols 2*tx + 32*u
    const int ty = t >> 4;          // 0..31, rows ty + 32*i
    const int m0 = blockIdx.x * 128;
    const int n0 = blockIdx.y * 128;
    const int b  = blockIdx.z;
    const float* xb = x + (size_t)b * (CDIM * NDIM);

    ull acc[4][4];
#pragma unroll
    for (int i = 0; i < 4; i++)
#pragma unroll
        for (int u = 0; u < 4; u++) acc[i][u] = 0ULL;

    for (int cc = 0; cc < CDIM; cc += 32) {
        // 512 threads load 32x128 Q (dup-stored) and 32x128 K. Coalesced.
#pragma unroll
        for (int k = 0; k < 8; k++) {
            int idx = t + k * 512;           // 0..4095
            int cl  = idx >> 7;
            int j   = idx & 127;
            float q = xb[(cc + cl) * NDIM + n0 + j];
            *(float2*)&Qd[cl][2 * j] = make_float2(q, q);  // 8B-strided STS.64
            Ks[cl][j] = xb[(cc + cl) * NDIM + m0 + j];
        }
        __syncthreads();

#pragma unroll
        for (int cl = 0; cl < 32; cl++) {
            ull b2[4];
#pragma unroll
            for (int u = 0; u < 4; u++)      // lanes 8B apart: conflict-free
                b2[u] = *(const ull*)&Ks[cl][2 * tx + 32 * u];
#pragma unroll
            for (int i = 0; i < 4; i++) {
                // (a,a) directly from dup'd smem — broadcast LDS.64, no pack
                ull a2 = *(const ull*)&Qd[cl][2 * (ty + 32 * i)];
#pragma unroll
                for (int u = 0; u < 4; u++) ffma2(acc[i][u], a2, b2[u]);
            }
        }
        __syncthreads();
    }

    float* arow = attn + (size_t)b * NN;
#pragma unroll
    for (int i = 0; i < 4; i++) {
        size_t base = (size_t)(n0 + ty + 32 * i) * NDIM + m0;
#pragma unroll
        for (int u = 0; u < 4; u++) {
            float lo, hi;
            unpack2(lo, hi, acc[i][u]);
            *(float2*)&arow[base + 2 * tx + 32 * u] = make_float2(lo, hi);
        }
    }
}

// ---------------------------------------------------------------------------
// K2: in-place row softmax (unchanged from the 1127us kernel — proven).
// One 128-thread block per (b, n) row; row register-resident.
// ---------------------------------------------------------------------------
__global__ __launch_bounds__(128)
void softmax_kernel(float* __restrict__ attn) {
    const int n = blockIdx.x;
    const int b = blockIdx.y;
    float4* row = (float4*)(attn + (size_t)b * NN + (size_t)n * NDIM);
    const int t = threadIdx.x;

    float4 v[8];
    float m = -1e30f;
#pragma unroll
    for (int k = 0; k < 8; k++) {
        v[k] = row[t + 128 * k];
        m = fmaxf(m, fmaxf(fmaxf(v[k].x, v[k].y), fmaxf(v[k].z, v[k].w)));
    }
#pragma unroll
    for (int o = 16; o > 0; o >>= 1)
        m = fmaxf(m, __shfl_xor_sync(0xffffffffu, m, o));

    __shared__ float smax[4];
    __shared__ float ssum[4];
    const int warp = t >> 5, lane = t & 31;
    if (lane == 0) smax[warp] = m;
    __syncthreads();
    m = fmaxf(fmaxf(smax[0], smax[1]), fmaxf(smax[2], smax[3]));

    float s = 0.0f;
#pragma unroll
    for (int k = 0; k < 8; k++) {
        v[k].x = __expf(v[k].x - m);
        v[k].y = __expf(v[k].y - m);
        v[k].z = __expf(v[k].z - m);
        v[k].w = __expf(v[k].w - m);
        s += (v[k].x + v[k].y) + (v[k].z + v[k].w);
    }
#pragma unroll
    for (int o = 16; o > 0; o >>= 1)
        s += __shfl_xor_sync(0xffffffffu, s, o);
    if (lane == 0) ssum[warp] = s;
    __syncthreads();
    s = (ssum[0] + ssum[1]) + (ssum[2] + ssum[3]);

    const float inv = 1.0f / s;
#pragma unroll
    for (int k = 0; k < 8; k++) {
        v[k].x *= inv; v[k].y *= inv; v[k].z *= inv; v[k].w *= inv;
        row[t + 128 * k] = v[k];
    }
}

// ---------------------------------------------------------------------------
// K3: y[b][c][n] = sum_m attn[b][n][m] * x[b][c][m]
// 128 n-rows x 64 c per CTA, 256 threads; m in chunks of 32.
// X stored DUPLICATED in smem (Xd[m][2c]=(v,v)): inner loop 4+4 LDS.64 +
// 16 FFMA2 = 24 instr (was 28 with packs). No attn writes here.
// ---------------------------------------------------------------------------
__global__ __launch_bounds__(256, 2)
void av_kernel(const float* __restrict__ x, const float* __restrict__ attn,
               float* __restrict__ y) {
    __shared__ float As[32][130];   // attn tile transposed: As[m][n-row]
    __shared__ float Xd[32][130];   // X tile, c duplicated: Xd[m][2c]=(v,v)

    const int t  = threadIdx.x;
    const int tx = t & 15;          // cols c = tx + 16*u
    const int ty = t >> 4;          // row pairs 2*ty + 32*i
    const int n0 = blockIdx.x * 128;
    const int b  = blockIdx.y;
    const float* xb = x + (size_t)b * (CDIM * NDIM);
    const float* ab = attn + (size_t)b * NN;

    ull acc[4][4];
#pragma unroll
    for (int i = 0; i < 4; i++)
#pragma unroll
        for (int u = 0; u < 4; u++) acc[i][u] = 0ULL;

    for (int m0 = 0; m0 < NDIM; m0 += 32) {
        // As[j][r] = attn[n0+r][m0+j] : coalesced LDG, 2-way STS (pitch 130)
#pragma unroll
        for (int kk = 0; kk < 16; kk++) {
            int idx = t + kk * 256;
            int r = idx >> 5;
            int j = idx & 31;
            As[j][r] = ab[(size_t)(n0 + r) * NDIM + m0 + j];
        }
        // Xd[j][2c] = dup of x[c][m0+j] : coalesced LDG, 8B STS
#pragma unroll
        for (int kk = 0; kk < 8; kk++) {
            int idx = t + kk * 256;
            int c = idx >> 5;
            int j = idx & 31;
            float v = xb[c * NDIM + m0 + j];
            *(float2*)&Xd[j][2 * c] = make_float2(v, v);
        }
        __syncthreads();

#pragma unroll
        for (int mm = 0; mm < 32; mm++) {
            ull a2[4];
#pragma unroll
            for (int i = 0; i < 4; i++)   // 8B-aligned n-row pairs
                a2[i] = *(const ull*)&As[mm][2 * ty + 32 * i];
#pragma unroll
            for (int u = 0; u < 4; u++) {
                // dup'd (v,v) directly from smem — 8B-strided, no pack
                ull b2 = *(const ull*)&Xd[mm][2 * (tx + 16 * u)];
#pragma unroll
                for (int i = 0; i < 4; i++) ffma2(acc[i][u], a2[i], b2);
            }
        }
        __syncthreads();
    }

#pragma unroll
    for (int u = 0; u < 4; u++) {
        int c = tx + 16 * u;
#pragma unroll
        for (int i = 0; i < 4; i++) {
            float lo, hi;
            unpack2(lo, hi, acc[i][u]);
            int n = n0 + 2 * ty + 32 * i;
            *(float2*)&y[(size_t)b * (CDIM * NDIM) + (size_t)c * NDIM + n] =
                make_float2(lo, hi);
        }
    }
}

// ---------------------------------------------------------------------------
// Launch. d_in[0] = x. d_out = [ y | attn ]. Graph-capturable, alloc-free.
// ---------------------------------------------------------------------------
extern "C" void kernel_launch(void* const* d_in, const int* in_sizes, int n_in,
                              void* d_out, int out_size) {
    (void)in_sizes; (void)n_in; (void)out_size;
    const float* x = (const float*)d_in[0];
    float* out  = (float*)d_out;
    float* y    = out;
    float* attn = out + Y_ELEMS;

    dim3 g1(NDIM / 128, NDIM / 128, BATCH);   // (32, 32, 8)
    scores_kernel<<<g1, 512>>>(x, attn);

    dim3 g2(NDIM, BATCH);                     // (4096, 8)
    softmax_kernel<<<g2, 128>>>(attn);

    dim3 g3(NDIM / 128, BATCH);               // (32, 8): one wave @ occ 2
    av_kernel<<<g3, 256>>>(x, attn, y);
}

// round 7
// speedup vs baseline: 1.2460x; 1.0003x over previous
#include <cuda_runtime.h>

// Problem: x [B=8, C=64, H=64, W=64], N = H*W = 4096
// out = [ y (B*C*N fp32) | attn (B*N*N fp32) ]
#define BATCH 8
#define CDIM  64
#define NDIM  4096
#define NN    (NDIM * NDIM)
#define Y_ELEMS (BATCH * CDIM * NDIM)

typedef unsigned long long ull;

// ---------------------------------------------------------------------------
// Packed f32x2 (sm_103a FFMA2 — 2x fp32 FMA throughput, PTX-only)
// ---------------------------------------------------------------------------
__device__ __forceinline__ void unpack2(float& lo, float& hi, ull v) {
    asm("mov.b64 {%0, %1}, %2;" : "=f"(lo), "=f"(hi) : "l"(v));
}
__device__ __forceinline__ void ffma2(ull& d, ull a, ull b) {
    asm("fma.rn.f32x2 %0, %1, %2, %0;" : "+l"(d) : "l"(a), "l"(b));
}

// ---------------------------------------------------------------------------
// K1: raw scores S[b][n][m] = sum_c x[b][c][n] * x[b][c][m]
// 128x128 tile per CTA, 512 threads (16x32), per-thread 4 rows x 4 col-pairs.
// Q stored DUPLICATED in smem so the dup'd FFMA2 operand is one broadcast
// LDS.64 (no packs). Inner loop: 4+4 LDS.64 + 16 FFMA2 = 24 instr, 67% fma.
// occ 2 => 32 warps/SM = 8/SMSP (vs 4 before) for latency hiding.
// ---------------------------------------------------------------------------
__global__ __launch_bounds__(512, 2)
void scores_kernel(const float* __restrict__ x, float* __restrict__ attn) {
    __shared__ float Qd[32][256];   // Q chunk, each value duplicated: (q,q)
    __shared__ float Ks[32][128];   // K chunk

    const int t  = threadIdx.x;
    const int tx = t & 15;          // col group: cols 2*tx + 32*u
    const int ty = t >> 4;          // 0..31, rows ty + 32*i
    const int m0 = blockIdx.x * 128;
    const int n0 = blockIdx.y * 128;
    const int b  = blockIdx.z;
    const float* xb = x + (size_t)b * (CDIM * NDIM);

    ull acc[4][4];
#pragma unroll
    for (int i = 0; i < 4; i++)
#pragma unroll
        for (int u = 0; u < 4; u++) acc[i][u] = 0ULL;

    for (int cc = 0; cc < CDIM; cc += 32) {
        // 512 threads load 32x128 Q (dup-stored) and 32x128 K. Coalesced.
#pragma unroll
        for (int k = 0; k < 8; k++) {
            int idx = t + k * 512;           // 0..4095
            int cl  = idx >> 7;
            int j   = idx & 127;
            float q = xb[(cc + cl) * NDIM + n0 + j];
            *(float2*)&Qd[cl][2 * j] = make_float2(q, q);  // 8B-strided STS.64
            Ks[cl][j] = xb[(cc + cl) * NDIM + m0 + j];
        }
        __syncthreads();

#pragma unroll
        for (int cl = 0; cl < 32; cl++) {
            ull b2[4];
#pragma unroll
            for (int u = 0; u < 4; u++)      // lanes 8B apart: conflict-free
                b2[u] = *(const ull*)&Ks[cl][2 * tx + 32 * u];
#pragma unroll
            for (int i = 0; i < 4; i++) {
                // (a,a) directly from dup'd smem — broadcast LDS.64, no pack
                ull a2 = *(const ull*)&Qd[cl][2 * (ty + 32 * i)];
#pragma unroll
                for (int u = 0; u < 4; u++) ffma2(acc[i][u], a2, b2[u]);
            }
        }
        __syncthreads();
    }

    float* arow = attn + (size_t)b * NN;
#pragma unroll
    for (int i = 0; i < 4; i++) {
        size_t base = (size_t)(n0 + ty + 32 * i) * NDIM + m0;
#pragma unroll
        for (int u = 0; u < 4; u++) {
            float lo, hi;
            unpack2(lo, hi, acc[i][u]);
            *(float2*)&arow[base + 2 * tx + 32 * u] = make_float2(lo, hi);
        }
    }
}

// ---------------------------------------------------------------------------
// K2: in-place row softmax (unchanged from the 1127us kernel — proven).
// One 128-thread block per (b, n) row; row register-resident.
// ---------------------------------------------------------------------------
__global__ __launch_bounds__(128)
void softmax_kernel(float* __restrict__ attn) {
    const int n = blockIdx.x;
    const int b = blockIdx.y;
    float4* row = (float4*)(attn + (size_t)b * NN + (size_t)n * NDIM);
    const int t = threadIdx.x;

    float4 v[8];
    float m = -1e30f;
#pragma unroll
    for (int k = 0; k < 8; k++) {
        v[k] = row[t + 128 * k];
        m = fmaxf(m, fmaxf(fmaxf(v[k].x, v[k].y), fmaxf(v[k].z, v[k].w)));
    }
#pragma unroll
    for (int o = 16; o > 0; o >>= 1)
        m = fmaxf(m, __shfl_xor_sync(0xffffffffu, m, o));

    __shared__ float smax[4];
    __shared__ float ssum[4];
    const int warp = t >> 5, lane = t & 31;
    if (lane == 0) smax[warp] = m;
    __syncthreads();
    m = fmaxf(fmaxf(smax[0], smax[1]), fmaxf(smax[2], smax[3]));

    float s = 0.0f;
#pragma unroll
    for (int k = 0; k < 8; k++) {
        v[k].x = __expf(v[k].x - m);
        v[k].y = __expf(v[k].y - m);
        v[k].z = __expf(v[k].z - m);
        v[k].w = __expf(v[k].w - m);
        s += (v[k].x + v[k].y) + (v[k].z + v[k].w);
    }
#pragma unroll
    for (int o = 16; o > 0; o >>= 1)
        s += __shfl_xor_sync(0xffffffffu, s, o);
    if (lane == 0) ssum[warp] = s;
    __syncthreads();
    s = (ssum[0] + ssum[1]) + (ssum[2] + ssum[3]);

    const float inv = 1.0f / s;
#pragma unroll
    for (int k = 0; k < 8; k++) {
        v[k].x *= inv; v[k].y *= inv; v[k].z *= inv; v[k].w *= inv;
        row[t + 128 * k] = v[k];
    }
}

// ---------------------------------------------------------------------------
// K3: y[b][c][n] = sum_m attn[b][n][m] * x[b][c][m]
// 128 n-rows x 64 c per CTA, 256 threads; m in chunks of 32.
// X stored DUPLICATED in smem (Xd[m][2c]=(v,v)): inner loop 4+4 LDS.64 +
// 16 FFMA2 = 24 instr (was 28 with packs). No attn writes here.
// ---------------------------------------------------------------------------
__global__ __launch_bounds__(256, 2)
void av_kernel(const float* __restrict__ x, const float* __restrict__ attn,
               float* __restrict__ y) {
    __shared__ float As[32][130];   // attn tile transposed: As[m][n-row]
    __shared__ float Xd[32][130];   // X tile, c duplicated: Xd[m][2c]=(v,v)

    const int t  = threadIdx.x;
    const int tx = t & 15;          // cols c = tx + 16*u
    const int ty = t >> 4;          // row pairs 2*ty + 32*i
    const int n0 = blockIdx.x * 128;
    const int b  = blockIdx.y;
    const float* xb = x + (size_t)b * (CDIM * NDIM);
    const float* ab = attn + (size_t)b * NN;

    ull acc[4][4];
#pragma unroll
    for (int i = 0; i < 4; i++)
#pragma unroll
        for (int u = 0; u < 4; u++) acc[i][u] = 0ULL;

    for (int m0 = 0; m0 < NDIM; m0 += 32) {
        // As[j][r] = attn[n0+r][m0+j] : coalesced LDG, 2-way STS (pitch 130)
#pragma unroll
        for (int kk = 0; kk < 16; kk++) {
            int idx = t + kk * 256;
            int r = idx >> 5;
            int j = idx & 31;
            As[j][r] = ab[(size_t)(n0 + r) * NDIM + m0 + j];
        }
        // Xd[j][2c] = dup of x[c][m0+j] : coalesced LDG, 8B STS
#pragma unroll
        for (int kk = 0; kk < 8; kk++) {
            int idx = t + kk * 256;
            int c = idx >> 5;
            int j = idx & 31;
            float v = xb[c * NDIM + m0 + j];
            *(float2*)&Xd[j][2 * c] = make_float2(v, v);
        }
        __syncthreads();

#pragma unroll
        for (int mm = 0; mm < 32; mm++) {
            ull a2[4];
#pragma unroll
            for (int i = 0; i < 4; i++)   // 8B-aligned n-row pairs
                a2[i] = *(const ull*)&As[mm][2 * ty + 32 * i];
#pragma unroll
            for (int u = 0; u < 4; u++) {
                // dup'd (v,v) directly from smem — 8B-strided, no pack
                ull b2 = *(const ull*)&Xd[mm][2 * (tx + 16 * u)];
#pragma unroll
                for (int i = 0; i < 4; i++) ffma2(acc[i][u], a2[i], b2);
            }
        }
        __syncthreads();
    }

#pragma unroll
    for (int u = 0; u < 4; u++) {
        int c = tx + 16 * u;
#pragma unroll
        for (int i = 0; i < 4; i++) {
            float lo, hi;
            unpack2(lo, hi, acc[i][u]);
            int n = n0 + 2 * ty + 32 * i;
            *(float2*)&y[(size_t)b * (CDIM * NDIM) + (size_t)c * NDIM + n] =
                make_float2(lo, hi);
        }
    }
}

// ---------------------------------------------------------------------------
// Launch. d_in[0] = x. d_out = [ y | attn ]. Graph-capturable, alloc-free.
// ---------------------------------------------------------------------------
extern "C" void kernel_launch(void* const* d_in, const int* in_sizes, int n_in,
                              void* d_out, int out_size) {
    (void)in_sizes; (void)n_in; (void)out_size;
    const float* x = (const float*)d_in[0];
    float* out  = (float*)d_out;
    float* y    = out;
    float* attn = out + Y_ELEMS;

    dim3 g1(NDIM / 128, NDIM / 128, BATCH);   // (32, 32, 8)
    scores_kernel<<<g1, 512>>>(x, attn);

    dim3 g2(NDIM, BATCH);                     // (4096, 8)
    softmax_kernel<<<g2, 128>>>(attn);

    dim3 g3(NDIM / 128, BATCH);               // (32, 8): one wave @ occ 2
    av_kernel<<<g3, 256>>>(x, attn, y);
}